// round 12
// baseline (speedup 1.0000x reference)
#include <cuda_runtime.h>
#include <cuda_bf16.h>
#include <cuda_fp16.h>
#include <cstdint>

#define Nn 32768
#define Dd 512
#define Cc 64
#define Kk 16
#define Mm 512
#define Jj 256   // C*DEPTH
#define TAU 2.5e-3f
#define FLAG_CAP 262144

// ---------------- scratch ----------------
__device__ unsigned char d_idx[Nn * Cc];             // [n][c]  2 MB (row-major!)
__device__ unsigned d_Lp16[64 * Cc * 32 * 2];        // packed fp16 stage2 B frags 1 MB
__device__ float d_Ih[Nn * Dd];                      // I tf32-hi, fragment order, 64 MB
__device__ float d_Ah[Dd * Jj];                      // A hi, fragment order, 512 KB
__device__ float d_Al[Dd * Jj];                      // A lo, 512 KB
__device__ unsigned d_flags[FLAG_CAP];
__device__ int d_flagCount;

__device__ __forceinline__ float f2tf(float f) {
    unsigned u;
    asm("cvt.rna.tf32.f32 %0, %1;" : "=r"(u) : "f"(f));
    return __uint_as_float(u);
}
__device__ __forceinline__ uint32_t smaddr(const void* p) {
    uint32_t a;
    asm("{ .reg .u64 t; cvta.to.shared.u64 t, %1; cvt.u32.u64 %0, t; }" : "=r"(a) : "l"(p));
    return a;
}
__device__ __forceinline__ void cpa16(uint32_t dst, const void* src) {
    asm volatile("cp.async.cg.shared.global [%0], [%1], 16;" :: "r"(dst), "l"(src) : "memory");
}
__device__ __forceinline__ void cp_commit() {
    asm volatile("cp.async.commit_group;" ::: "memory");
}
template <int N> __device__ __forceinline__ void cp_wait() {
    asm volatile("cp.async.wait_group %0;" :: "n"(N) : "memory");
}

// ---------------- K_pack: L -> packed fp16 fragment layout; zero flag count ----------------
__global__ void k_pack(const float* __restrict__ L) {
    if (blockIdx.x == 0 && threadIdx.x == 0) d_flagCount = 0;
    int i = blockIdx.x * 256 + threadIdx.x;        // 262144 pairs
    int m = i >> 9;
    int k = (i & 511) * 2;
    float2 f = *(const float2*)&L[(size_t)m * 1024 + k];
    __half h0 = __float2half_rn(f.x), h1 = __float2half_rn(f.y);
    unsigned hv = ((unsigned)*(unsigned short*)&h1 << 16) | *(unsigned short*)&h0;
    int c = k >> 4, kk = k & 15;
    int t4 = (kk >> 1) & 3, rb = kk >> 3;
    int lane = (m & 7) * 4 + t4, mt = m >> 3;
    d_Lp16[(((mt * Cc + c) * 32) + lane) * 2 + rb] = hv;
}

// ---------------- K_splitI: I -> tf32 hi in fragment order (smem-staged, coalesced) ----
__global__ __launch_bounds__(256) void k_splitI(const float* __restrict__ I) {
    __shared__ float tile[128 * 36];
    int tid = threadIdx.x;
    int nT = blockIdx.x >> 4, ktI = blockIdx.x & 15;
#pragma unroll
    for (int q = 0; q < 4; q++) {
        int idx = q * 256 + tid;
        int row = idx >> 3, c4 = idx & 7;
        float4 v = *(const float4*)&I[(size_t)(nT * 128 + row) * Dd + ktI * 32 + c4 * 4];
        tile[row * 36 + c4 * 4 + 0] = v.x;
        tile[row * 36 + c4 * 4 + 1] = v.y;
        tile[row * 36 + c4 * 4 + 2] = v.z;
        tile[row * 36 + c4 * 4 + 3] = v.w;
    }
    __syncthreads();
#pragma unroll
    for (int q = 0; q < 4; q++) {
        int pos = q * 256 + tid;
        int mt = pos >> 7, ch = (pos >> 5) & 3, lane = pos & 31;
        int rowb = mt * 16 + (lane >> 2);
        int kb = ch * 8 + (lane & 3);
        float4 h;
        h.x = f2tf(tile[rowb * 36 + kb]);
        h.y = f2tf(tile[(rowb + 8) * 36 + kb]);
        h.z = f2tf(tile[rowb * 36 + kb + 4]);
        h.w = f2tf(tile[(rowb + 8) * 36 + kb + 4]);
        *(float4*)&d_Ih[((size_t)blockIdx.x * 1024 + pos) * 4] = h;
    }
}

// ---------------- K_packA: A -> tf32 hi/lo in MMA B-fragment tile order ----------------
__global__ void k_packA(const float* __restrict__ A) {
    int g = blockIdx.x * 256 + threadIdx.x;
    int jT = g >> 15, ktI = (g >> 11) & 15, pos = g & 2047;
    int n8 = pos >> 7, ch = (pos >> 5) & 3, lane = pos & 31;
    int j = jT * 128 + n8 * 8 + (lane >> 2);
    int k0 = ktI * 32 + ch * 8 + (lane & 3);
    float a0 = A[(size_t)k0 * Jj + j];
    float a1 = A[(size_t)(k0 + 4) * Jj + j];
    float2 h, l;
    h.x = f2tf(a0); l.x = f2tf(a0 - h.x);
    h.y = f2tf(a1); l.y = f2tf(a1 - h.y);
    *(float2*)&d_Ah[(size_t)g * 2] = h;
    *(float2*)&d_Al[(size_t)g * 2] = l;
}

// ---------------- K1: 2-pass TF32 mma GEMM, cp.async double-buffered ----------------
#define MMA_TF32(d, a, b) \
    asm volatile("mma.sync.aligned.m16n8k8.row.col.f32.tf32.tf32.f32 " \
                 "{%0,%1,%2,%3},{%4,%5,%6,%7},{%8,%9},{%0,%1,%2,%3};" \
                 : "+f"(d[0]), "+f"(d[1]), "+f"(d[2]), "+f"(d[3]) \
                 : "r"(a[0]), "r"(a[1]), "r"(a[2]), "r"(a[3]), "r"(b[0]), "r"(b[1]))

#define G1_SMEM 98304   // 2 x 48 KB stage buffers; epilogue Psm (67.6 KB) fits

__global__ __launch_bounds__(256) void k_gemm_tf32(const float* __restrict__ Tg)
{
    extern __shared__ float smf[];

    int tid = threadIdx.x, lane = tid & 31, wid = tid >> 5;
    int wm = wid & 1, wn = wid >> 1;
    int g = lane >> 2, t4 = lane & 3;
    int nT = blockIdx.y, jT = blockIdx.x;
    int nBase = nT * 128;
    uint32_t sb = smaddr(smf);

    float acc[4][4][4];
#pragma unroll
    for (int mt = 0; mt < 4; mt++)
#pragma unroll
        for (int nt = 0; nt < 4; nt++)
#pragma unroll
            for (int q = 0; q < 4; q++) acc[mt][nt][q] = 0.f;

#define COPY_TILE(kt, buf)                                                        \
    do {                                                                          \
        const char* gIh = (const char*)&d_Ih[(size_t)(nT * 16 + (kt)) * 4096];    \
        const char* gAh = (const char*)&d_Ah[(size_t)(jT * 16 + (kt)) * 4096];    \
        const char* gAl = (const char*)&d_Al[(size_t)(jT * 16 + (kt)) * 4096];    \
        uint32_t d0 = sb + (buf) * 49152;                                         \
        _Pragma("unroll")                                                         \
        for (int q = 0; q < 4; q++) {                                             \
            int bo = (q * 256 + tid) * 16;                                        \
            cpa16(d0 + bo,         gIh + bo);                                     \
            cpa16(d0 + 16384 + bo, gAh + bo);                                     \
            cpa16(d0 + 32768 + bo, gAl + bo);                                     \
        }                                                                         \
        cp_commit();                                                              \
    } while (0)

    COPY_TILE(0, 0);

    for (int kt = 0; kt < 16; kt++) {
        if (kt < 15) {
            COPY_TILE(kt + 1, (kt + 1) & 1);
            cp_wait<1>();
        } else {
            cp_wait<0>();
        }
        __syncthreads();

        const float* bIh = smf + (kt & 1) * 12288;
        const float* bAh = bIh + 4096;
        const float* bAl = bIh + 8192;

#pragma unroll
        for (int ch = 0; ch < 4; ch++) {
            unsigned ih[4][4], bh[4][2], bl[4][2];
#pragma unroll
            for (int mt = 0; mt < 4; mt++) {
                int off = (((wm * 4 + mt) * 4 + ch) * 32 + lane) * 4;
                float4 vh = *(const float4*)&bIh[off];
                ih[mt][0] = __float_as_uint(vh.x); ih[mt][1] = __float_as_uint(vh.y);
                ih[mt][2] = __float_as_uint(vh.z); ih[mt][3] = __float_as_uint(vh.w);
            }
#pragma unroll
            for (int nt = 0; nt < 4; nt++) {
                int off = (((wn * 4 + nt) * 4 + ch) * 32 + lane) * 2;
                float2 vh = *(const float2*)&bAh[off];
                float2 vl = *(const float2*)&bAl[off];
                bh[nt][0] = __float_as_uint(vh.x); bh[nt][1] = __float_as_uint(vh.y);
                bl[nt][0] = __float_as_uint(vl.x); bl[nt][1] = __float_as_uint(vl.y);
            }
#pragma unroll
            for (int mt = 0; mt < 4; mt++)
#pragma unroll
                for (int nt = 0; nt < 4; nt++) {
                    MMA_TF32(acc[mt][nt], ih[mt], bh[nt]);
                    MMA_TF32(acc[mt][nt], ih[mt], bl[nt]);
                }
        }
        __syncthreads();
    }

    // ---- epilogue: P -> smem (reuse stage buffers) ----
    float* Psm = smf;   // [128][132]
#pragma unroll
    for (int mt = 0; mt < 4; mt++)
#pragma unroll
        for (int nt = 0; nt < 4; nt++) {
            int row = wm * 64 + mt * 16 + g;
            int col = wn * 32 + nt * 8 + t4 * 2;
            Psm[row * 132 + col]           = acc[mt][nt][0];
            Psm[row * 132 + col + 1]       = acc[mt][nt][1];
            Psm[(row + 8) * 132 + col]     = acc[mt][nt][2];
            Psm[(row + 8) * 132 + col + 1] = acc[mt][nt][3];
        }
    __syncthreads();

    // ---- traversal with borderline flagging; writes row-major d_idx[n][c] ----
    int cb = tid & 31, rg = tid >> 5;   // lane == cb -> coalesced byte stores
    int c = jT * 32 + cb;
    const float* Tc = &Tg[c * 15];
#pragma unroll
    for (int rr = 0; rr < 16; rr++) {
        int row = rg * 16 + rr;
        float4 fv = *(const float4*)&Psm[row * 132 + cb * 4];
        float f[4] = {fv.x, fv.y, fv.z, fv.w};
        unsigned node = 0, kidx = 0;
        float minabs = 1e30f;
#pragma unroll
        for (int l = 0; l < 4; l++) {
            float d = f[l] - __ldg(&Tc[node]);
            float ad = fabsf(d);
            minabs = (ad < minabs) ? ad : minabs;
            unsigned bit = (d > 0.f) ? 1u : 0u;
            kidx = (kidx << 1) | bit;
            node = 2 * node + 1 + bit;
        }
        if (minabs < TAU) {
            int slot = atomicAdd(&d_flagCount, 1);
            if (slot < FLAG_CAP)
                d_flags[slot] = ((unsigned)(nBase + row) << 6) | (unsigned)c;
        }
        d_idx[(size_t)(nBase + row) * Cc + c] = (unsigned char)kidx;
    }
}

// ---------------- K1b: exact fp32 fixup for borderline codebooks ----------------
__global__ __launch_bounds__(256) void k_fixup(
    const float* __restrict__ I, const float* __restrict__ A,
    const float* __restrict__ Tg)
{
    int lane = threadIdx.x & 31;
    int wg = blockIdx.x * 8 + (threadIdx.x >> 5);
    int cnt = d_flagCount;
    if (cnt > FLAG_CAP) cnt = FLAG_CAP;
    for (int e = wg; e < cnt; e += 64 * 8) {
        unsigned v = d_flags[e];
        int n = v >> 6, c = v & 63;
        float a0 = 0.f, a1 = 0.f, a2 = 0.f, a3 = 0.f;
        for (int s = 0; s < 16; s++) {
            int k = s * 32 + lane;
            float iv = I[(size_t)n * Dd + k];
            float4 av = *(const float4*)&A[(size_t)k * Jj + c * 4];
            a0 = fmaf(iv, av.x, a0);
            a1 = fmaf(iv, av.y, a1);
            a2 = fmaf(iv, av.z, a2);
            a3 = fmaf(iv, av.w, a3);
        }
#pragma unroll
        for (int off = 16; off > 0; off >>= 1) {
            a0 += __shfl_xor_sync(0xffffffffu, a0, off);
            a1 += __shfl_xor_sync(0xffffffffu, a1, off);
            a2 += __shfl_xor_sync(0xffffffffu, a2, off);
            a3 += __shfl_xor_sync(0xffffffffu, a3, off);
        }
        if (lane == 0) {
            float f[4] = {a0, a1, a2, a3};
            const float* Tc = &Tg[c * 15];
            unsigned node = 0, kidx = 0;
#pragma unroll
            for (int l = 0; l < 4; l++) {
                unsigned bit = (f[l] > __ldg(&Tc[node])) ? 1u : 0u;
                kidx = (kidx << 1) | bit;
                node = 2 * node + 1 + bit;
            }
            d_idx[(size_t)n * Cc + c] = (unsigned char)kidx;
        }
    }
}

// ---------------- K2: fp16 HMMA one-hot GEMM, reg-resident idx (LDS.128 x16 c) ----------
#define S2_BPK   0
#define S2_IDX   131072                // Bpk = 128 KB
#define IDXPITCH 80                    // 64 idx bytes + 16 pad (conflict-free LDS.128)
#define IDXBUF   (256 * IDXPITCH)      // 20480
#define S2_SMEM  (S2_IDX + 2 * IDXBUF) // 172032 -> 1 CTA/SM

#define NSPLIT 16
#define NPER   (Nn / NSPLIT)           // 2048
#define NROWS  256

__global__ __launch_bounds__(512) void k_lutmma(float* __restrict__ out)
{
    extern __shared__ char sm[];
    unsigned* Bpk = (unsigned*)(sm + S2_BPK);    // [ms8][c64][lane32][2] fp16x2
    uint32_t sb = smaddr(sm);

    int tid  = threadIdx.x;
    int wid  = tid >> 5;
    int lane = tid & 31;
    int g    = lane >> 2;
    int t4   = lane & 3;

    int mBase  = blockIdx.x * 64;
    int nRange = blockIdx.y * NPER;

    {   // copy packed fp16 B slice: 128 KB contiguous (8 mt groups)
        const uint4* src = (const uint4*)&d_Lp16[(size_t)(mBase >> 3) * Cc * 64];
        uint4* dst = (uint4*)Bpk;
        for (int i = tid; i < 8192; i += 512) dst[i] = src[i];
    }

    // idx tile: 256 rows x 64 B (gmem contiguous) -> smem rows pitched 80
#define COPY_IDX(it, buf)                                                          \
    do {                                                                           \
        int nb_ = nRange + (it) * NROWS;                                           \
        int row_ = tid >> 1, half_ = (tid & 1) * 32;                               \
        uint32_t d0 = sb + S2_IDX + (buf) * IDXBUF + row_ * IDXPITCH + half_;      \
        const char* s0 = (const char*)d_idx + (size_t)(nb_ + row_) * Cc + half_;   \
        cpa16(d0, s0);                                                             \
        cpa16(d0 + 16, s0 + 16);                                                   \
        cp_commit();                                                               \
    } while (0)

    COPY_IDX(0, 0);
    __syncthreads();   // Bpk ready

    int n0loc = wid * 16 + g;
    for (int it = 0; it < NPER / NROWS; it++) {
        if (it < NPER / NROWS - 1) {
            COPY_IDX(it + 1, (it + 1) & 1);
            cp_wait<1>();
        } else {
            cp_wait<0>();
        }
        __syncthreads();
        const char* idxs = sm + S2_IDX + (it & 1) * IDXBUF;
        int nb = nRange + it * NROWS;

        float acc[8][4];
#pragma unroll
        for (int ms = 0; ms < 8; ms++)
#pragma unroll
            for (int q = 0; q < 4; q++) acc[ms][q] = 0.f;

        const uint4* row0 = (const uint4*)(idxs + n0loc * IDXPITCH);
        const uint4* row1 = (const uint4*)(idxs + (n0loc + 8) * IDXPITCH);

#pragma unroll 1
        for (int cq = 0; cq < 4; cq++) {
            uint4 w0 = row0[cq];
            uint4 w1 = row1[cq];
            unsigned q0[4] = {w0.x, w0.y, w0.z, w0.w};
            unsigned q1[4] = {w1.x, w1.y, w1.z, w1.w};
#pragma unroll
            for (int jw = 0; jw < 4; jw++) {
#pragma unroll
                for (int jb = 0; jb < 4; jb++) {
                    int c = cq * 16 + jw * 4 + jb;
                    unsigned i0 = (q0[jw] >> (8 * jb)) & 255u;
                    unsigned i1 = (q1[jw] >> (8 * jb)) & 255u;
                    unsigned s0 = 0x3C00u << ((i0 & 1) << 4);   // fp16 1.0
                    unsigned s1 = 0x3C00u << ((i1 & 1) << 4);
                    unsigned h0 = i0 >> 1, h1 = i1 >> 1;
                    unsigned a0 = (h0 == (unsigned)t4)     ? s0 : 0u;
                    unsigned a1 = (h1 == (unsigned)t4)     ? s1 : 0u;
                    unsigned a2 = (h0 == (unsigned)t4 + 4) ? s0 : 0u;
                    unsigned a3 = (h1 == (unsigned)t4 + 4) ? s1 : 0u;

#pragma unroll
                    for (int ms = 0; ms < 8; ms++) {
                        uint2 b2 = *(const uint2*)&Bpk[(((ms * Cc + c) * 32) + lane) * 2];
                        asm volatile(
                            "mma.sync.aligned.m16n8k16.row.col.f32.f16.f16.f32 "
                            "{%0,%1,%2,%3}, {%4,%5,%6,%7}, {%8,%9}, {%0,%1,%2,%3};"
                            : "+f"(acc[ms][0]), "+f"(acc[ms][1]),
                              "+f"(acc[ms][2]), "+f"(acc[ms][3])
                            : "r"(a0), "r"(a1), "r"(a2), "r"(a3), "r"(b2.x), "r"(b2.y));
                    }
                }
            }
        }

        int nA = nb + n0loc;
#pragma unroll
        for (int ms = 0; ms < 8; ms++) {
            float2 v0 = make_float2(acc[ms][0], acc[ms][1]);
            float2 v1 = make_float2(acc[ms][2], acc[ms][3]);
            *(float2*)&out[(size_t)nA * Mm + mBase + ms * 8 + t4 * 2] = v0;
            *(float2*)&out[(size_t)(nA + 8) * Mm + mBase + ms * 8 + t4 * 2] = v1;
        }
        __syncthreads();
    }
}

// ---------------- launch ----------------
extern "C" void kernel_launch(void* const* d_in, const int* in_sizes, int n_in,
                              void* d_out, int out_size) {
    const float *I = nullptr, *T = nullptr, *L = nullptr, *A = nullptr;
    for (int i = 0; i < n_in; i++) {
        switch (in_sizes[i]) {
            case Nn * Dd:      I = (const float*)d_in[i]; break;
            case 960:          T = (const float*)d_in[i]; break;
            case Mm * Cc * Kk: L = (const float*)d_in[i]; break;
            case Dd * Jj:      A = (const float*)d_in[i]; break;
            default: break;  // S, B unused — tree structure hardcoded
        }
    }
    float* out = (float*)d_out;

    cudaFuncSetAttribute(k_gemm_tf32, cudaFuncAttributeMaxDynamicSharedMemorySize, G1_SMEM);
    cudaFuncSetAttribute(k_lutmma,    cudaFuncAttributeMaxDynamicSharedMemorySize, S2_SMEM);

    k_pack<<<(Mm * Cc * Kk / 2) / 256, 256>>>(L);
    k_splitI<<<4096, 256>>>(I);
    k_packA<<<(Dd * Jj / 2) / 256, 256>>>(A);

    dim3 g1(2, Nn / 128);           // (2 jT, 256 nT)
    k_gemm_tf32<<<g1, 256, G1_SMEM>>>(T);

    k_fixup<<<64, 256>>>(I, A, T);

    dim3 g2(Mm / 64, NSPLIT);       // (8, 16)
    k_lutmma<<<g2, 512, S2_SMEM>>>(out);
}

// round 13
// speedup vs baseline: 1.0336x; 1.0336x over previous
#include <cuda_runtime.h>
#include <cuda_bf16.h>
#include <cuda_fp16.h>
#include <cstdint>

#define Nn 32768
#define Dd 512
#define Cc 64
#define Kk 16
#define Mm 512
#define Jj 256   // C*DEPTH
#define TAU 2.5e-3f
#define FLAG_CAP 262144

// ---------------- scratch ----------------
__device__ unsigned char d_idxT[Cc * Nn];            // [c][n]  2 MB
__device__ unsigned d_Lp16[64 * Cc * 32 * 2];        // packed fp16 stage2 B frags 1 MB
__device__ float d_Ih[Nn * Dd];                      // I tf32-hi, fragment order, 64 MB
__device__ float d_Ah[Dd * Jj];                      // A hi, fragment order, 512 KB
__device__ float d_Al[Dd * Jj];                      // A lo, 512 KB
__device__ unsigned d_flags[FLAG_CAP];
__device__ int d_flagCount;

__device__ __forceinline__ float f2tf(float f) {
    unsigned u;
    asm("cvt.rna.tf32.f32 %0, %1;" : "=r"(u) : "f"(f));
    return __uint_as_float(u);
}
__device__ __forceinline__ uint32_t smaddr(const void* p) {
    uint32_t a;
    asm("{ .reg .u64 t; cvta.to.shared.u64 t, %1; cvt.u32.u64 %0, t; }" : "=r"(a) : "l"(p));
    return a;
}
__device__ __forceinline__ void cpa16(uint32_t dst, const void* src) {
    asm volatile("cp.async.cg.shared.global [%0], [%1], 16;" :: "r"(dst), "l"(src) : "memory");
}
__device__ __forceinline__ void cp_commit() {
    asm volatile("cp.async.commit_group;" ::: "memory");
}
template <int N> __device__ __forceinline__ void cp_wait() {
    asm volatile("cp.async.wait_group %0;" :: "n"(N) : "memory");
}

// ---------------- K_pack: L -> packed fp16 fragment layout; zero flag count ----------------
__global__ void k_pack(const float* __restrict__ L) {
    if (blockIdx.x == 0 && threadIdx.x == 0) d_flagCount = 0;
    int i = blockIdx.x * 256 + threadIdx.x;        // 262144 pairs
    int m = i >> 9;
    int k = (i & 511) * 2;
    float2 f = *(const float2*)&L[(size_t)m * 1024 + k];
    __half h0 = __float2half_rn(f.x), h1 = __float2half_rn(f.y);
    unsigned hv = ((unsigned)*(unsigned short*)&h1 << 16) | *(unsigned short*)&h0;
    int c = k >> 4, kk = k & 15;
    int t4 = (kk >> 1) & 3, rb = kk >> 3;
    int lane = (m & 7) * 4 + t4, mt = m >> 3;
    d_Lp16[(((mt * Cc + c) * 32) + lane) * 2 + rb] = hv;
}

// ---------------- K_splitI: I -> tf32 hi in fragment order (smem-staged, coalesced) ----
__global__ __launch_bounds__(256) void k_splitI(const float* __restrict__ I) {
    __shared__ float tile[128 * 36];
    int tid = threadIdx.x;
    int nT = blockIdx.x >> 4, ktI = blockIdx.x & 15;
#pragma unroll
    for (int q = 0; q < 4; q++) {
        int idx = q * 256 + tid;
        int row = idx >> 3, c4 = idx & 7;
        float4 v = *(const float4*)&I[(size_t)(nT * 128 + row) * Dd + ktI * 32 + c4 * 4];
        tile[row * 36 + c4 * 4 + 0] = v.x;
        tile[row * 36 + c4 * 4 + 1] = v.y;
        tile[row * 36 + c4 * 4 + 2] = v.z;
        tile[row * 36 + c4 * 4 + 3] = v.w;
    }
    __syncthreads();
#pragma unroll
    for (int q = 0; q < 4; q++) {
        int pos = q * 256 + tid;
        int mt = pos >> 7, ch = (pos >> 5) & 3, lane = pos & 31;
        int rowb = mt * 16 + (lane >> 2);
        int kb = ch * 8 + (lane & 3);
        float4 h;
        h.x = f2tf(tile[rowb * 36 + kb]);
        h.y = f2tf(tile[(rowb + 8) * 36 + kb]);
        h.z = f2tf(tile[rowb * 36 + kb + 4]);
        h.w = f2tf(tile[(rowb + 8) * 36 + kb + 4]);
        *(float4*)&d_Ih[((size_t)blockIdx.x * 1024 + pos) * 4] = h;
    }
}

// ---------------- K_packA: A -> tf32 hi/lo in MMA B-fragment tile order ----------------
__global__ void k_packA(const float* __restrict__ A) {
    int g = blockIdx.x * 256 + threadIdx.x;
    int jT = g >> 15, ktI = (g >> 11) & 15, pos = g & 2047;
    int n8 = pos >> 7, ch = (pos >> 5) & 3, lane = pos & 31;
    int j = jT * 128 + n8 * 8 + (lane >> 2);
    int k0 = ktI * 32 + ch * 8 + (lane & 3);
    float a0 = A[(size_t)k0 * Jj + j];
    float a1 = A[(size_t)(k0 + 4) * Jj + j];
    float2 h, l;
    h.x = f2tf(a0); l.x = f2tf(a0 - h.x);
    h.y = f2tf(a1); l.y = f2tf(a1 - h.y);
    *(float2*)&d_Ah[(size_t)g * 2] = h;
    *(float2*)&d_Al[(size_t)g * 2] = l;
}

// ---------------- K1: 2-pass TF32 mma GEMM, cp.async double-buffered ----------------
#define MMA_TF32(d, a, b) \
    asm volatile("mma.sync.aligned.m16n8k8.row.col.f32.tf32.tf32.f32 " \
                 "{%0,%1,%2,%3},{%4,%5,%6,%7},{%8,%9},{%0,%1,%2,%3};" \
                 : "+f"(d[0]), "+f"(d[1]), "+f"(d[2]), "+f"(d[3]) \
                 : "r"(a[0]), "r"(a[1]), "r"(a[2]), "r"(a[3]), "r"(b[0]), "r"(b[1]))

#define G1_SMEM 98304   // 2 x 48 KB stage buffers; epilogue Psm (67.6 KB) fits

__global__ __launch_bounds__(256) void k_gemm_tf32(const float* __restrict__ Tg)
{
    extern __shared__ float smf[];

    int tid = threadIdx.x, lane = tid & 31, wid = tid >> 5;
    int wm = wid & 1, wn = wid >> 1;
    int g = lane >> 2, t4 = lane & 3;
    int nT = blockIdx.y, jT = blockIdx.x;
    int nBase = nT * 128;
    uint32_t sb = smaddr(smf);

    float acc[4][4][4];
#pragma unroll
    for (int mt = 0; mt < 4; mt++)
#pragma unroll
        for (int nt = 0; nt < 4; nt++)
#pragma unroll
            for (int q = 0; q < 4; q++) acc[mt][nt][q] = 0.f;

#define COPY_TILE(kt, buf)                                                        \
    do {                                                                          \
        const char* gIh = (const char*)&d_Ih[(size_t)(nT * 16 + (kt)) * 4096];    \
        const char* gAh = (const char*)&d_Ah[(size_t)(jT * 16 + (kt)) * 4096];    \
        const char* gAl = (const char*)&d_Al[(size_t)(jT * 16 + (kt)) * 4096];    \
        uint32_t d0 = sb + (buf) * 49152;                                         \
        _Pragma("unroll")                                                         \
        for (int q = 0; q < 4; q++) {                                             \
            int bo = (q * 256 + tid) * 16;                                        \
            cpa16(d0 + bo,         gIh + bo);                                     \
            cpa16(d0 + 16384 + bo, gAh + bo);                                     \
            cpa16(d0 + 32768 + bo, gAl + bo);                                     \
        }                                                                         \
        cp_commit();                                                              \
    } while (0)

    COPY_TILE(0, 0);

    for (int kt = 0; kt < 16; kt++) {
        if (kt < 15) {
            COPY_TILE(kt + 1, (kt + 1) & 1);
            cp_wait<1>();
        } else {
            cp_wait<0>();
        }
        __syncthreads();

        const float* bIh = smf + (kt & 1) * 12288;
        const float* bAh = bIh + 4096;
        const float* bAl = bIh + 8192;

#pragma unroll
        for (int ch = 0; ch < 4; ch++) {
            unsigned ih[4][4], bh[4][2], bl[4][2];
#pragma unroll
            for (int mt = 0; mt < 4; mt++) {
                int off = (((wm * 4 + mt) * 4 + ch) * 32 + lane) * 4;
                float4 vh = *(const float4*)&bIh[off];
                ih[mt][0] = __float_as_uint(vh.x); ih[mt][1] = __float_as_uint(vh.y);
                ih[mt][2] = __float_as_uint(vh.z); ih[mt][3] = __float_as_uint(vh.w);
            }
#pragma unroll
            for (int nt = 0; nt < 4; nt++) {
                int off = (((wn * 4 + nt) * 4 + ch) * 32 + lane) * 2;
                float2 vh = *(const float2*)&bAh[off];
                float2 vl = *(const float2*)&bAl[off];
                bh[nt][0] = __float_as_uint(vh.x); bh[nt][1] = __float_as_uint(vh.y);
                bl[nt][0] = __float_as_uint(vl.x); bl[nt][1] = __float_as_uint(vl.y);
            }
#pragma unroll
            for (int mt = 0; mt < 4; mt++)
#pragma unroll
                for (int nt = 0; nt < 4; nt++) {
                    MMA_TF32(acc[mt][nt], ih[mt], bh[nt]);
                    MMA_TF32(acc[mt][nt], ih[mt], bl[nt]);
                }
        }
        __syncthreads();
    }

    // ---- epilogue: P -> smem (reuse stage buffers) ----
    float* Psm = smf;   // [128][132]
#pragma unroll
    for (int mt = 0; mt < 4; mt++)
#pragma unroll
        for (int nt = 0; nt < 4; nt++) {
            int row = wm * 64 + mt * 16 + g;
            int col = wn * 32 + nt * 8 + t4 * 2;
            Psm[row * 132 + col]           = acc[mt][nt][0];
            Psm[row * 132 + col + 1]       = acc[mt][nt][1];
            Psm[(row + 8) * 132 + col]     = acc[mt][nt][2];
            Psm[(row + 8) * 132 + col + 1] = acc[mt][nt][3];
        }
    __syncthreads();

    // ---- traversal with borderline flagging ----
    int cb = tid & 31, rg = tid >> 5;
    int c = jT * 32 + cb;
    const float* Tc = &Tg[c * 15];
#pragma unroll
    for (int h8 = 0; h8 < 2; h8++) {
        unsigned long long pk = 0;
#pragma unroll
        for (int rr = 0; rr < 8; rr++) {
            int row = rg * 16 + h8 * 8 + rr;
            float4 fv = *(const float4*)&Psm[row * 132 + cb * 4];
            float f[4] = {fv.x, fv.y, fv.z, fv.w};
            unsigned node = 0, kidx = 0;
            float minabs = 1e30f;
#pragma unroll
            for (int l = 0; l < 4; l++) {
                float d = f[l] - __ldg(&Tc[node]);
                float ad = fabsf(d);
                minabs = (ad < minabs) ? ad : minabs;
                unsigned bit = (d > 0.f) ? 1u : 0u;
                kidx = (kidx << 1) | bit;
                node = 2 * node + 1 + bit;
            }
            pk |= (unsigned long long)kidx << (8 * rr);
            if (minabs < TAU) {
                int slot = atomicAdd(&d_flagCount, 1);
                if (slot < FLAG_CAP)
                    d_flags[slot] = ((unsigned)(nBase + row) << 6) | (unsigned)c;
            }
        }
        *(unsigned long long*)&d_idxT[(size_t)c * Nn + nBase + rg * 16 + h8 * 8] = pk;
    }
}

// ---------------- K1b: exact fp32 fixup for borderline codebooks ----------------
__global__ __launch_bounds__(256) void k_fixup(
    const float* __restrict__ I, const float* __restrict__ A,
    const float* __restrict__ Tg)
{
    int lane = threadIdx.x & 31;
    int wg = blockIdx.x * 8 + (threadIdx.x >> 5);
    int cnt = d_flagCount;
    if (cnt > FLAG_CAP) cnt = FLAG_CAP;
    for (int e = wg; e < cnt; e += 64 * 8) {
        unsigned v = d_flags[e];
        int n = v >> 6, c = v & 63;
        float a0 = 0.f, a1 = 0.f, a2 = 0.f, a3 = 0.f;
        for (int s = 0; s < 16; s++) {
            int k = s * 32 + lane;
            float iv = I[(size_t)n * Dd + k];
            float4 av = *(const float4*)&A[(size_t)k * Jj + c * 4];
            a0 = fmaf(iv, av.x, a0);
            a1 = fmaf(iv, av.y, a1);
            a2 = fmaf(iv, av.z, a2);
            a3 = fmaf(iv, av.w, a3);
        }
#pragma unroll
        for (int off = 16; off > 0; off >>= 1) {
            a0 += __shfl_xor_sync(0xffffffffu, a0, off);
            a1 += __shfl_xor_sync(0xffffffffu, a1, off);
            a2 += __shfl_xor_sync(0xffffffffu, a2, off);
            a3 += __shfl_xor_sync(0xffffffffu, a3, off);
        }
        if (lane == 0) {
            float f[4] = {a0, a1, a2, a3};
            const float* Tc = &Tg[c * 15];
            unsigned node = 0, kidx = 0;
#pragma unroll
            for (int l = 0; l < 4; l++) {
                unsigned bit = (f[l] > __ldg(&Tc[node])) ? 1u : 0u;
                kidx = (kidx << 1) | bit;
                node = 2 * node + 1 + bit;
            }
            d_idxT[(size_t)c * Nn + n] = (unsigned char)kidx;
        }
    }
}

// ---------------- K2: fp16 HMMA one-hot GEMM, dual row-group per warp ----------------
// Each warp owns rows n0 = wid*16+g and n0+256 within a 512-row iteration;
// every B-frag LDS.64 feeds TWO HMMAs.
#define S2_BPK   0
#define S2_IDX   131072                 // Bpk = 128 KB
#define IDXBUF   (Cc * 512)             // 32 KB per buffer, [c][512 rows]
#define S2_SMEM  (S2_IDX + 2 * IDXBUF)  // 196608 -> 1 CTA/SM

#define NSPLIT 16
#define NPER   (Nn / NSPLIT)            // 2048
#define NROWS  512

__global__ __launch_bounds__(512) void k_lutmma(float* __restrict__ out)
{
    extern __shared__ char sm[];
    unsigned* Bpk = (unsigned*)(sm + S2_BPK);    // [ms8][c64][lane32][2] fp16x2
    uint32_t sb = smaddr(sm);

    int tid  = threadIdx.x;
    int wid  = tid >> 5;
    int lane = tid & 31;
    int g    = lane >> 2;
    int t4   = lane & 3;

    int mBase  = blockIdx.x * 64;
    int nRange = blockIdx.y * NPER;

    {   // copy packed fp16 B slice: 128 KB contiguous (8 mt groups)
        const uint4* src = (const uint4*)&d_Lp16[(size_t)(mBase >> 3) * Cc * 64];
        uint4* dst = (uint4*)Bpk;
        for (int i = tid; i < 8192; i += 512) dst[i] = src[i];
    }

    // idx tile: 64 c x 512 rows = 32 KB, 4 cp.async/thread
#define COPY_IDX(it, buf)                                                          \
    do {                                                                           \
        int nb_ = nRange + (it) * NROWS;                                           \
        int c_ = tid >> 3, off_ = (tid & 7) * 64;                                  \
        uint32_t d0 = sb + S2_IDX + (buf) * IDXBUF + c_ * 512 + off_;              \
        const char* s0 = (const char*)&d_idxT[(size_t)c_ * Nn + nb_ + off_];       \
        cpa16(d0,      s0);                                                        \
        cpa16(d0 + 16, s0 + 16);                                                   \
        cpa16(d0 + 32, s0 + 32);                                                   \
        cpa16(d0 + 48, s0 + 48);                                                   \
        cp_commit();                                                               \
    } while (0)

    COPY_IDX(0, 0);
    __syncthreads();   // Bpk ready

    int n0 = wid * 16 + g;          // 0..255
    int n1 = n0 + 256;              // 256..511
    for (int it = 0; it < NPER / NROWS; it++) {
        if (it < NPER / NROWS - 1) {
            COPY_IDX(it + 1, (it + 1) & 1);
            cp_wait<1>();
        } else {
            cp_wait<0>();
        }
        __syncthreads();
        const unsigned char* idxs = (const unsigned char*)(sm + S2_IDX + (it & 1) * IDXBUF);
        int nb = nRange + it * NROWS;

        float acc[2][8][4];
#pragma unroll
        for (int r = 0; r < 2; r++)
#pragma unroll
            for (int ms = 0; ms < 8; ms++)
#pragma unroll
                for (int q = 0; q < 4; q++) acc[r][ms][q] = 0.f;

#pragma unroll 2
        for (int c = 0; c < Cc; c++) {
            const unsigned char* ic = idxs + c * 512;
            // row-group A (rows n0, n0+8)
            unsigned i0 = ic[n0], i1 = ic[n0 + 8];
            unsigned sA0 = 0x3C00u << ((i0 & 1) << 4);
            unsigned sA1 = 0x3C00u << ((i1 & 1) << 4);
            unsigned hA0 = i0 >> 1, hA1 = i1 >> 1;
            unsigned A0 = (hA0 == (unsigned)t4)     ? sA0 : 0u;
            unsigned A1 = (hA1 == (unsigned)t4)     ? sA1 : 0u;
            unsigned A2 = (hA0 == (unsigned)t4 + 4) ? sA0 : 0u;
            unsigned A3 = (hA1 == (unsigned)t4 + 4) ? sA1 : 0u;
            // row-group B (rows n1, n1+8)
            unsigned j0 = ic[n1], j1 = ic[n1 + 8];
            unsigned sB0 = 0x3C00u << ((j0 & 1) << 4);
            unsigned sB1 = 0x3C00u << ((j1 & 1) << 4);
            unsigned hB0 = j0 >> 1, hB1 = j1 >> 1;
            unsigned B0 = (hB0 == (unsigned)t4)     ? sB0 : 0u;
            unsigned B1 = (hB1 == (unsigned)t4)     ? sB1 : 0u;
            unsigned B2 = (hB0 == (unsigned)t4 + 4) ? sB0 : 0u;
            unsigned B3 = (hB1 == (unsigned)t4 + 4) ? sB1 : 0u;

#pragma unroll
            for (int ms = 0; ms < 8; ms++) {
                uint2 b2 = *(const uint2*)&Bpk[(((ms * Cc + c) * 32) + lane) * 2];
                asm volatile(
                    "mma.sync.aligned.m16n8k16.row.col.f32.f16.f16.f32 "
                    "{%0,%1,%2,%3}, {%4,%5,%6,%7}, {%8,%9}, {%0,%1,%2,%3};"
                    : "+f"(acc[0][ms][0]), "+f"(acc[0][ms][1]),
                      "+f"(acc[0][ms][2]), "+f"(acc[0][ms][3])
                    : "r"(A0), "r"(A1), "r"(A2), "r"(A3), "r"(b2.x), "r"(b2.y));
                asm volatile(
                    "mma.sync.aligned.m16n8k16.row.col.f32.f16.f16.f32 "
                    "{%0,%1,%2,%3}, {%4,%5,%6,%7}, {%8,%9}, {%0,%1,%2,%3};"
                    : "+f"(acc[1][ms][0]), "+f"(acc[1][ms][1]),
                      "+f"(acc[1][ms][2]), "+f"(acc[1][ms][3])
                    : "r"(B0), "r"(B1), "r"(B2), "r"(B3), "r"(b2.x), "r"(b2.y));
            }
        }

#pragma unroll
        for (int r = 0; r < 2; r++) {
            int nA = nb + (r == 0 ? n0 : n1);
#pragma unroll
            for (int ms = 0; ms < 8; ms++) {
                float2 v0 = make_float2(acc[r][ms][0], acc[r][ms][1]);
                float2 v1 = make_float2(acc[r][ms][2], acc[r][ms][3]);
                *(float2*)&out[(size_t)nA * Mm + mBase + ms * 8 + t4 * 2] = v0;
                *(float2*)&out[(size_t)(nA + 8) * Mm + mBase + ms * 8 + t4 * 2] = v1;
            }
        }
        __syncthreads();
    }
}

// ---------------- launch ----------------
extern "C" void kernel_launch(void* const* d_in, const int* in_sizes, int n_in,
                              void* d_out, int out_size) {
    const float *I = nullptr, *T = nullptr, *L = nullptr, *A = nullptr;
    for (int i = 0; i < n_in; i++) {
        switch (in_sizes[i]) {
            case Nn * Dd:      I = (const float*)d_in[i]; break;
            case 960:          T = (const float*)d_in[i]; break;
            case Mm * Cc * Kk: L = (const float*)d_in[i]; break;
            case Dd * Jj:      A = (const float*)d_in[i]; break;
            default: break;  // S, B unused — tree structure hardcoded
        }
    }
    float* out = (float*)d_out;

    cudaFuncSetAttribute(k_gemm_tf32, cudaFuncAttributeMaxDynamicSharedMemorySize, G1_SMEM);
    cudaFuncSetAttribute(k_lutmma,    cudaFuncAttributeMaxDynamicSharedMemorySize, S2_SMEM);

    k_pack<<<(Mm * Cc * Kk / 2) / 256, 256>>>(L);
    k_splitI<<<4096, 256>>>(I);
    k_packA<<<(Dd * Jj / 2) / 256, 256>>>(A);

    dim3 g1(2, Nn / 128);           // (2 jT, 256 nT)
    k_gemm_tf32<<<g1, 256, G1_SMEM>>>(T);

    k_fixup<<<64, 256>>>(I, A, T);

    dim3 g2(Mm / 64, NSPLIT);       // (8, 16)
    k_lutmma<<<g2, 512, S2_SMEM>>>(out);
}

// round 15
// speedup vs baseline: 1.2054x; 1.1662x over previous
#include <cuda_runtime.h>
#include <cuda_bf16.h>
#include <cuda_fp16.h>
#include <cstdint>

#define Nn 32768
#define Dd 512
#define Cc 64
#define Kk 16
#define Mm 512
#define Jj 256   // C*DEPTH
#define TAU 2.5e-3f
#define FLAG_CAP 262144

// ---------------- scratch ----------------
__device__ unsigned char d_idxT[Cc * Nn];            // [c][n]  2 MB
__device__ unsigned d_Lp16[64 * Cc * 32 * 2];        // packed fp16 stage2 B frags 1 MB
__device__ float d_Ah[Dd * Jj];                      // A hi, fragment order, 512 KB
__device__ float d_Al[Dd * Jj];                      // A lo, 512 KB
__device__ unsigned d_flags[FLAG_CAP];
__device__ int d_flagCount;

__device__ __forceinline__ float f2tf(float f) {
    unsigned u;
    asm("cvt.rna.tf32.f32 %0, %1;" : "=r"(u) : "f"(f));
    return __uint_as_float(u);
}
__device__ __forceinline__ uint32_t smaddr(const void* p) {
    uint32_t a;
    asm("{ .reg .u64 t; cvta.to.shared.u64 t, %1; cvt.u32.u64 %0, t; }" : "=r"(a) : "l"(p));
    return a;
}
__device__ __forceinline__ void cpa16(uint32_t dst, const void* src) {
    asm volatile("cp.async.cg.shared.global [%0], [%1], 16;" :: "r"(dst), "l"(src) : "memory");
}
__device__ __forceinline__ void cp_commit() {
    asm volatile("cp.async.commit_group;" ::: "memory");
}
template <int N> __device__ __forceinline__ void cp_wait() {
    asm volatile("cp.async.wait_group %0;" :: "n"(N) : "memory");
}

// ---------------- K_pack: L -> packed fp16 fragment layout; zero flag count ----------------
__global__ void k_pack(const float* __restrict__ L) {
    if (blockIdx.x == 0 && threadIdx.x == 0) d_flagCount = 0;
    int i = blockIdx.x * 256 + threadIdx.x;        // 262144 pairs
    int m = i >> 9;
    int k = (i & 511) * 2;
    float2 f = *(const float2*)&L[(size_t)m * 1024 + k];
    __half h0 = __float2half_rn(f.x), h1 = __float2half_rn(f.y);
    unsigned hv = ((unsigned)*(unsigned short*)&h1 << 16) | *(unsigned short*)&h0;
    int c = k >> 4, kk = k & 15;
    int t4 = (kk >> 1) & 3, rb = kk >> 3;
    int lane = (m & 7) * 4 + t4, mt = m >> 3;
    d_Lp16[(((mt * Cc + c) * 32) + lane) * 2 + rb] = hv;
}

// ---------------- K_packA: A -> tf32 hi/lo in MMA B-fragment tile order ----------------
__global__ void k_packA(const float* __restrict__ A) {
    int g = blockIdx.x * 256 + threadIdx.x;
    int jT = g >> 15, ktI = (g >> 11) & 15, pos = g & 2047;
    int n8 = pos >> 7, ch = (pos >> 5) & 3, lane = pos & 31;
    int j = jT * 128 + n8 * 8 + (lane >> 2);
    int k0 = ktI * 32 + ch * 8 + (lane & 3);
    float a0 = A[(size_t)k0 * Jj + j];
    float a1 = A[(size_t)(k0 + 4) * Jj + j];
    float2 h, l;
    h.x = f2tf(a0); l.x = f2tf(a0 - h.x);
    h.y = f2tf(a1); l.y = f2tf(a1 - h.y);
    *(float2*)&d_Ah[(size_t)g * 2] = h;
    *(float2*)&d_Al[(size_t)g * 2] = l;
}

// ---------------- K1: 2-pass TF32 mma GEMM, raw-I fused conversion ----------------
#define MMA_TF32(d, a, b) \
    asm volatile("mma.sync.aligned.m16n8k8.row.col.f32.tf32.tf32.f32 " \
                 "{%0,%1,%2,%3},{%4,%5,%6,%7},{%8,%9},{%0,%1,%2,%3};" \
                 : "+f"(d[0]), "+f"(d[1]), "+f"(d[2]), "+f"(d[3]) \
                 : "r"(a[0]), "r"(a[1]), "r"(a[2]), "r"(a[3]), "r"(b[0]), "r"(b[1]))

// stage: raw I tile 128x32 fp32 pitch-36 (18432 B) | Ah (16384) | Al (16384)
#define ST_I    0
#define ST_AH   18432
#define ST_AL   34816
#define ST_SZ   51200
#define G1_SMEM (2 * ST_SZ)   // 102400; epilogue Psm (67.6 KB) fits

__global__ __launch_bounds__(256) void k_gemm_tf32(
    const float* __restrict__ I, const float* __restrict__ Tg)
{
    extern __shared__ float smf[];

    int tid = threadIdx.x, lane = tid & 31, wid = tid >> 5;
    int wm = wid & 1, wn = wid >> 1;
    int g = lane >> 2, t4 = lane & 3;
    int nT = blockIdx.y, jT = blockIdx.x;
    int nBase = nT * 128;
    uint32_t sb = smaddr(smf);

    float acc[4][4][4];
#pragma unroll
    for (int mt = 0; mt < 4; mt++)
#pragma unroll
        for (int nt = 0; nt < 4; nt++)
#pragma unroll
            for (int q = 0; q < 4; q++) acc[mt][nt][q] = 0.f;

#define COPY_TILE(kt, buf)                                                        \
    do {                                                                          \
        const char* gAh = (const char*)&d_Ah[(size_t)(jT * 16 + (kt)) * 4096];    \
        const char* gAl = (const char*)&d_Al[(size_t)(jT * 16 + (kt)) * 4096];    \
        uint32_t d0 = sb + (buf) * ST_SZ;                                         \
        _Pragma("unroll")                                                         \
        for (int q = 0; q < 4; q++) {                                             \
            int chunk = q * 256 + tid;                                            \
            int row = chunk >> 3, c8 = chunk & 7;                                 \
            cpa16(d0 + ST_I + row * 144 + c8 * 16,                                \
                  (const char*)&I[(size_t)(nBase + row) * Dd + (kt) * 32] + c8 * 16); \
        }                                                                         \
        _Pragma("unroll")                                                         \
        for (int q = 0; q < 4; q++) {                                             \
            int bo = (q * 256 + tid) * 16;                                        \
            cpa16(d0 + ST_AH + bo, gAh + bo);                                     \
            cpa16(d0 + ST_AL + bo, gAl + bo);                                     \
        }                                                                         \
        cp_commit();                                                              \
    } while (0)

    COPY_TILE(0, 0);

    for (int kt = 0; kt < 16; kt++) {
        if (kt < 15) {
            COPY_TILE(kt + 1, (kt + 1) & 1);
            cp_wait<1>();
        } else {
            cp_wait<0>();
        }
        __syncthreads();

        const float* ti  = smf + (kt & 1) * (ST_SZ / 4);            // raw I, pitch 36
        const float* bAh = smf + (kt & 1) * (ST_SZ / 4) + ST_AH / 4;
        const float* bAl = smf + (kt & 1) * (ST_SZ / 4) + ST_AL / 4;

#pragma unroll
        for (int ch = 0; ch < 4; ch++) {
            unsigned ih[4][4], bh[4][2], bl[4][2];
#pragma unroll
            for (int mt = 0; mt < 4; mt++) {
                int r0 = wm * 64 + mt * 16 + g;
                int col = ch * 8 + t4;
                ih[mt][0] = __float_as_uint(f2tf(ti[r0 * 36 + col]));
                ih[mt][1] = __float_as_uint(f2tf(ti[(r0 + 8) * 36 + col]));
                ih[mt][2] = __float_as_uint(f2tf(ti[r0 * 36 + col + 4]));
                ih[mt][3] = __float_as_uint(f2tf(ti[(r0 + 8) * 36 + col + 4]));
            }
#pragma unroll
            for (int nt = 0; nt < 4; nt++) {
                int off = (((wn * 4 + nt) * 4 + ch) * 32 + lane) * 2;
                float2 vh = *(const float2*)&bAh[off];
                float2 vl = *(const float2*)&bAl[off];
                bh[nt][0] = __float_as_uint(vh.x); bh[nt][1] = __float_as_uint(vh.y);
                bl[nt][0] = __float_as_uint(vl.x); bl[nt][1] = __float_as_uint(vl.y);
            }
#pragma unroll
            for (int mt = 0; mt < 4; mt++)
#pragma unroll
                for (int nt = 0; nt < 4; nt++) {
                    MMA_TF32(acc[mt][nt], ih[mt], bh[nt]);
                    MMA_TF32(acc[mt][nt], ih[mt], bl[nt]);
                }
        }
        __syncthreads();
    }

    // ---- epilogue: P -> smem (reuse stage buffers) ----
    float* Psm = smf;   // [128][132]
#pragma unroll
    for (int mt = 0; mt < 4; mt++)
#pragma unroll
        for (int nt = 0; nt < 4; nt++) {
            int row = wm * 64 + mt * 16 + g;
            int col = wn * 32 + nt * 8 + t4 * 2;
            Psm[row * 132 + col]           = acc[mt][nt][0];
            Psm[row * 132 + col + 1]       = acc[mt][nt][1];
            Psm[(row + 8) * 132 + col]     = acc[mt][nt][2];
            Psm[(row + 8) * 132 + col + 1] = acc[mt][nt][3];
        }
    __syncthreads();

    // ---- traversal with borderline flagging ----
    int cb = tid & 31, rg = tid >> 5;
    int c = jT * 32 + cb;
    const float* Tc = &Tg[c * 15];
#pragma unroll
    for (int h8 = 0; h8 < 2; h8++) {
        unsigned long long pk = 0;
#pragma unroll
        for (int rr = 0; rr < 8; rr++) {
            int row = rg * 16 + h8 * 8 + rr;
            float4 fv = *(const float4*)&Psm[row * 132 + cb * 4];
            float f[4] = {fv.x, fv.y, fv.z, fv.w};
            unsigned node = 0, kidx = 0;
            float minabs = 1e30f;
#pragma unroll
            for (int l = 0; l < 4; l++) {
                float d = f[l] - __ldg(&Tc[node]);
                float ad = fabsf(d);
                minabs = (ad < minabs) ? ad : minabs;
                unsigned bit = (d > 0.f) ? 1u : 0u;
                kidx = (kidx << 1) | bit;
                node = 2 * node + 1 + bit;
            }
            pk |= (unsigned long long)kidx << (8 * rr);
            if (minabs < TAU) {
                int slot = atomicAdd(&d_flagCount, 1);
                if (slot < FLAG_CAP)
                    d_flags[slot] = ((unsigned)(nBase + row) << 6) | (unsigned)c;
            }
        }
        *(unsigned long long*)&d_idxT[(size_t)c * Nn + nBase + rg * 16 + h8 * 8] = pk;
    }
}

// ---------------- K1b: exact fp32 fixup for borderline codebooks ----------------
__global__ __launch_bounds__(256) void k_fixup(
    const float* __restrict__ I, const float* __restrict__ A,
    const float* __restrict__ Tg)
{
    int lane = threadIdx.x & 31;
    int wg = blockIdx.x * 8 + (threadIdx.x >> 5);
    int cnt = d_flagCount;
    if (cnt > FLAG_CAP) cnt = FLAG_CAP;
    for (int e = wg; e < cnt; e += 64 * 8) {
        unsigned v = d_flags[e];
        int n = v >> 6, c = v & 63;
        float a0 = 0.f, a1 = 0.f, a2 = 0.f, a3 = 0.f;
        for (int s = 0; s < 16; s++) {
            int k = s * 32 + lane;
            float iv = I[(size_t)n * Dd + k];
            float4 av = *(const float4*)&A[(size_t)k * Jj + c * 4];
            a0 = fmaf(iv, av.x, a0);
            a1 = fmaf(iv, av.y, a1);
            a2 = fmaf(iv, av.z, a2);
            a3 = fmaf(iv, av.w, a3);
        }
#pragma unroll
        for (int off = 16; off > 0; off >>= 1) {
            a0 += __shfl_xor_sync(0xffffffffu, a0, off);
            a1 += __shfl_xor_sync(0xffffffffu, a1, off);
            a2 += __shfl_xor_sync(0xffffffffu, a2, off);
            a3 += __shfl_xor_sync(0xffffffffu, a3, off);
        }
        if (lane == 0) {
            float f[4] = {a0, a1, a2, a3};
            const float* Tc = &Tg[c * 15];
            unsigned node = 0, kidx = 0;
#pragma unroll
            for (int l = 0; l < 4; l++) {
                unsigned bit = (f[l] > __ldg(&Tc[node])) ? 1u : 0u;
                kidx = (kidx << 1) | bit;
                node = 2 * node + 1 + bit;
            }
            d_idxT[(size_t)c * Nn + n] = (unsigned char)kidx;
        }
    }
}

// ---------------- K2: fp16 HMMA one-hot GEMM (R11 best-measured config) ----------------
#define S2_BPK  0
#define S2_IDX  131072                 // Bpk = 128 KB
#define S2_SMEM (S2_IDX + 2 * 16384)   // 163840 -> 1 CTA/SM

#define NSPLIT 16
#define NPER   (Nn / NSPLIT)           // 2048
#define NROWS  256

__global__ __launch_bounds__(512) void k_lutmma(float* __restrict__ out)
{
    extern __shared__ char sm[];
    unsigned* Bpk = (unsigned*)(sm + S2_BPK);    // [ms8][c64][lane32][2] fp16x2
    uint32_t sb = smaddr(sm);

    int tid  = threadIdx.x;
    int wid  = tid >> 5;
    int lane = tid & 31;
    int g    = lane >> 2;
    int t4   = lane & 3;

    int mBase  = blockIdx.x * 64;
    int nRange = blockIdx.y * NPER;

    {   // copy packed fp16 B slice: 128 KB contiguous (8 mt groups)
        const uint4* src = (const uint4*)&d_Lp16[(size_t)(mBase >> 3) * Cc * 64];
        uint4* dst = (uint4*)Bpk;
        for (int i = tid; i < 8192; i += 512) dst[i] = src[i];
    }

#define COPY_IDX(it, buf)                                                          \
    do {                                                                           \
        int nb_ = nRange + (it) * NROWS;                                           \
        int c_ = tid >> 3, off_ = (tid & 7) * 32;                                  \
        uint32_t d0 = sb + S2_IDX + (buf) * 16384 + c_ * NROWS + off_;             \
        const char* s0 = (const char*)&d_idxT[(size_t)c_ * Nn + nb_ + off_];       \
        cpa16(d0, s0);                                                             \
        cpa16(d0 + 16, s0 + 16);                                                   \
        cp_commit();                                                               \
    } while (0)

    COPY_IDX(0, 0);
    __syncthreads();   // Bpk ready

    int n0loc = wid * 16 + g;
    for (int it = 0; it < NPER / NROWS; it++) {
        if (it < NPER / NROWS - 1) {
            COPY_IDX(it + 1, (it + 1) & 1);
            cp_wait<1>();
        } else {
            cp_wait<0>();
        }
        __syncthreads();
        const unsigned char* idxs = (const unsigned char*)(sm + S2_IDX + (it & 1) * 16384);
        int nb = nRange + it * NROWS;

        float acc[8][4];
#pragma unroll
        for (int ms = 0; ms < 8; ms++)
#pragma unroll
            for (int q = 0; q < 4; q++) acc[ms][q] = 0.f;

#pragma unroll 2
        for (int c = 0; c < Cc; c++) {
            unsigned i0 = idxs[c * NROWS + n0loc];
            unsigned i1 = idxs[c * NROWS + n0loc + 8];
            unsigned s0 = 0x3C00u << ((i0 & 1) << 4);   // fp16 1.0
            unsigned s1 = 0x3C00u << ((i1 & 1) << 4);
            unsigned h0 = i0 >> 1, h1 = i1 >> 1;
            unsigned a0 = (h0 == (unsigned)t4)     ? s0 : 0u;
            unsigned a1 = (h1 == (unsigned)t4)     ? s1 : 0u;
            unsigned a2 = (h0 == (unsigned)t4 + 4) ? s0 : 0u;
            unsigned a3 = (h1 == (unsigned)t4 + 4) ? s1 : 0u;

#pragma unroll
            for (int ms = 0; ms < 8; ms++) {
                uint2 b2 = *(const uint2*)&Bpk[(((ms * Cc + c) * 32) + lane) * 2];
                asm volatile(
                    "mma.sync.aligned.m16n8k16.row.col.f32.f16.f16.f32 "
                    "{%0,%1,%2,%3}, {%4,%5,%6,%7}, {%8,%9}, {%0,%1,%2,%3};"
                    : "+f"(acc[ms][0]), "+f"(acc[ms][1]), "+f"(acc[ms][2]), "+f"(acc[ms][3])
                    : "r"(a0), "r"(a1), "r"(a2), "r"(a3), "r"(b2.x), "r"(b2.y));
            }
        }

        int nA = nb + n0loc;
#pragma unroll
        for (int ms = 0; ms < 8; ms++) {
            float2 v0 = make_float2(acc[ms][0], acc[ms][1]);
            float2 v1 = make_float2(acc[ms][2], acc[ms][3]);
            *(float2*)&out[(size_t)nA * Mm + mBase + ms * 8 + t4 * 2] = v0;
            *(float2*)&out[(size_t)(nA + 8) * Mm + mBase + ms * 8 + t4 * 2] = v1;
        }
        __syncthreads();
    }
}

// ---------------- launch ----------------
extern "C" void kernel_launch(void* const* d_in, const int* in_sizes, int n_in,
                              void* d_out, int out_size) {
    const float *I = nullptr, *T = nullptr, *L = nullptr, *A = nullptr;
    for (int i = 0; i < n_in; i++) {
        switch (in_sizes[i]) {
            case Nn * Dd:      I = (const float*)d_in[i]; break;
            case 960:          T = (const float*)d_in[i]; break;
            case Mm * Cc * Kk: L = (const float*)d_in[i]; break;
            case Dd * Jj:      A = (const float*)d_in[i]; break;
            default: break;  // S, B unused — tree structure hardcoded
        }
    }
    float* out = (float*)d_out;

    cudaFuncSetAttribute(k_gemm_tf32, cudaFuncAttributeMaxDynamicSharedMemorySize, G1_SMEM);
    cudaFuncSetAttribute(k_lutmma,    cudaFuncAttributeMaxDynamicSharedMemorySize, S2_SMEM);

    k_pack<<<(Mm * Cc * Kk / 2) / 256, 256>>>(L);
    k_packA<<<(Dd * Jj / 2) / 256, 256>>>(A);

    dim3 g1(2, Nn / 128);           // (2 jT, 256 nT)
    k_gemm_tf32<<<g1, 256, G1_SMEM>>>(I, T);

    k_fixup<<<64, 256>>>(I, A, T);

    dim3 g2(Mm / 64, NSPLIT);       // (8, 16)
    k_lutmma<<<g2, 512, S2_SMEM>>>(out);
}

// round 16
// speedup vs baseline: 1.4454x; 1.1991x over previous
#include <cuda_runtime.h>
#include <cuda_bf16.h>
#include <cuda_fp16.h>
#include <cstdint>

#define Nn 32768
#define Dd 512
#define Cc 64
#define Kk 16
#define Mm 512
#define Jj 256   // C*DEPTH
#define TAU 2.5e-3f
#define FLAG_CAP 262144

// ---------------- scratch ----------------
__device__ unsigned char d_idxT[Cc * Nn];            // [c][n]  2 MB
__device__ unsigned d_Lp16[64 * Cc * 32 * 2];        // packed fp16 stage2 B frags 1 MB
__device__ float d_Ah[Dd * Jj];                      // A hi, fragment order, 512 KB
__device__ float d_Al[Dd * Jj];                      // A lo, 512 KB
__device__ unsigned d_flags[FLAG_CAP];
__device__ int d_flagCount;

__device__ __forceinline__ float f2tf(float f) {
    unsigned u;
    asm("cvt.rna.tf32.f32 %0, %1;" : "=r"(u) : "f"(f));
    return __uint_as_float(u);
}
__device__ __forceinline__ uint32_t smaddr(const void* p) {
    uint32_t a;
    asm("{ .reg .u64 t; cvta.to.shared.u64 t, %1; cvt.u32.u64 %0, t; }" : "=r"(a) : "l"(p));
    return a;
}
__device__ __forceinline__ void cpa16(uint32_t dst, const void* src) {
    asm volatile("cp.async.cg.shared.global [%0], [%1], 16;" :: "r"(dst), "l"(src) : "memory");
}
__device__ __forceinline__ void cp_commit() {
    asm volatile("cp.async.commit_group;" ::: "memory");
}
template <int N> __device__ __forceinline__ void cp_wait() {
    asm volatile("cp.async.wait_group %0;" :: "n"(N) : "memory");
}

// ---------------- K_pack: L -> packed fp16 fragment layout; zero flag count ----------------
__global__ void k_pack(const float* __restrict__ L) {
    if (blockIdx.x == 0 && threadIdx.x == 0) d_flagCount = 0;
    int i = blockIdx.x * 256 + threadIdx.x;        // 262144 pairs
    int m = i >> 9;
    int k = (i & 511) * 2;
    float2 f = *(const float2*)&L[(size_t)m * 1024 + k];
    __half h0 = __float2half_rn(f.x), h1 = __float2half_rn(f.y);
    unsigned hv = ((unsigned)*(unsigned short*)&h1 << 16) | *(unsigned short*)&h0;
    int c = k >> 4, kk = k & 15;
    int t4 = (kk >> 1) & 3, rb = kk >> 3;
    int lane = (m & 7) * 4 + t4, mt = m >> 3;
    d_Lp16[(((mt * Cc + c) * 32) + lane) * 2 + rb] = hv;
}

// ---------------- K_packA: A -> tf32 hi/lo in MMA B-fragment tile order ----------------
__global__ void k_packA(const float* __restrict__ A) {
    int g = blockIdx.x * 256 + threadIdx.x;
    int jT = g >> 15, ktI = (g >> 11) & 15, pos = g & 2047;
    int n8 = pos >> 7, ch = (pos >> 5) & 3, lane = pos & 31;
    int j = jT * 128 + n8 * 8 + (lane >> 2);
    int k0 = ktI * 32 + ch * 8 + (lane & 3);
    float a0 = A[(size_t)k0 * Jj + j];
    float a1 = A[(size_t)(k0 + 4) * Jj + j];
    float2 h, l;
    h.x = f2tf(a0); l.x = f2tf(a0 - h.x);
    h.y = f2tf(a1); l.y = f2tf(a1 - h.y);
    *(float2*)&d_Ah[(size_t)g * 2] = h;
    *(float2*)&d_Al[(size_t)g * 2] = l;
}

// ---------------- K1: 2-pass TF32 mma GEMM, raw-I fused conversion ----------------
#define MMA_TF32(d, a, b) \
    asm volatile("mma.sync.aligned.m16n8k8.row.col.f32.tf32.tf32.f32 " \
                 "{%0,%1,%2,%3},{%4,%5,%6,%7},{%8,%9},{%0,%1,%2,%3};" \
                 : "+f"(d[0]), "+f"(d[1]), "+f"(d[2]), "+f"(d[3]) \
                 : "r"(a[0]), "r"(a[1]), "r"(a[2]), "r"(a[3]), "r"(b[0]), "r"(b[1]))

// stage: raw I tile 128x32 fp32 pitch-36 (18432 B) | Ah (16384) | Al (16384)
#define ST_I    0
#define ST_AH   18432
#define ST_AL   34816
#define ST_SZ   51200
#define G1_SMEM (2 * ST_SZ)   // 102400; epilogue Psm (67.6 KB) fits

__global__ __launch_bounds__(256) void k_gemm_tf32(
    const float* __restrict__ I, const float* __restrict__ Tg)
{
    extern __shared__ float smf[];

    int tid = threadIdx.x, lane = tid & 31, wid = tid >> 5;
    int wm = wid & 1, wn = wid >> 1;
    int g = lane >> 2, t4 = lane & 3;
    int nT = blockIdx.y, jT = blockIdx.x;
    int nBase = nT * 128;
    uint32_t sb = smaddr(smf);

    float acc[4][4][4];
#pragma unroll
    for (int mt = 0; mt < 4; mt++)
#pragma unroll
        for (int nt = 0; nt < 4; nt++)
#pragma unroll
            for (int q = 0; q < 4; q++) acc[mt][nt][q] = 0.f;

#define COPY_TILE(kt, buf)                                                        \
    do {                                                                          \
        const char* gAh = (const char*)&d_Ah[(size_t)(jT * 16 + (kt)) * 4096];    \
        const char* gAl = (const char*)&d_Al[(size_t)(jT * 16 + (kt)) * 4096];    \
        uint32_t d0 = sb + (buf) * ST_SZ;                                         \
        _Pragma("unroll")                                                         \
        for (int q = 0; q < 4; q++) {                                             \
            int chunk = q * 256 + tid;                                            \
            int row = chunk >> 3, c8 = chunk & 7;                                 \
            cpa16(d0 + ST_I + row * 144 + c8 * 16,                                \
                  (const char*)&I[(size_t)(nBase + row) * Dd + (kt) * 32] + c8 * 16); \
        }                                                                         \
        _Pragma("unroll")                                                         \
        for (int q = 0; q < 4; q++) {                                             \
            int bo = (q * 256 + tid) * 16;                                        \
            cpa16(d0 + ST_AH + bo, gAh + bo);                                     \
            cpa16(d0 + ST_AL + bo, gAl + bo);                                     \
        }                                                                         \
        cp_commit();                                                              \
    } while (0)

    COPY_TILE(0, 0);

    for (int kt = 0; kt < 16; kt++) {
        if (kt < 15) {
            COPY_TILE(kt + 1, (kt + 1) & 1);
            cp_wait<1>();
        } else {
            cp_wait<0>();
        }
        __syncthreads();

        const float* ti  = smf + (kt & 1) * (ST_SZ / 4);            // raw I, pitch 36
        const float* bAh = smf + (kt & 1) * (ST_SZ / 4) + ST_AH / 4;
        const float* bAl = smf + (kt & 1) * (ST_SZ / 4) + ST_AL / 4;

#pragma unroll
        for (int ch = 0; ch < 4; ch++) {
            unsigned ih[4][4], bh[4][2], bl[4][2];
#pragma unroll
            for (int mt = 0; mt < 4; mt++) {
                int r0 = wm * 64 + mt * 16 + g;
                int col = ch * 8 + t4;
                ih[mt][0] = __float_as_uint(f2tf(ti[r0 * 36 + col]));
                ih[mt][1] = __float_as_uint(f2tf(ti[(r0 + 8) * 36 + col]));
                ih[mt][2] = __float_as_uint(f2tf(ti[r0 * 36 + col + 4]));
                ih[mt][3] = __float_as_uint(f2tf(ti[(r0 + 8) * 36 + col + 4]));
            }
#pragma unroll
            for (int nt = 0; nt < 4; nt++) {
                int off = (((wn * 4 + nt) * 4 + ch) * 32 + lane) * 2;
                float2 vh = *(const float2*)&bAh[off];
                float2 vl = *(const float2*)&bAl[off];
                bh[nt][0] = __float_as_uint(vh.x); bh[nt][1] = __float_as_uint(vh.y);
                bl[nt][0] = __float_as_uint(vl.x); bl[nt][1] = __float_as_uint(vl.y);
            }
#pragma unroll
            for (int mt = 0; mt < 4; mt++)
#pragma unroll
                for (int nt = 0; nt < 4; nt++) {
                    MMA_TF32(acc[mt][nt], ih[mt], bh[nt]);
                    MMA_TF32(acc[mt][nt], ih[mt], bl[nt]);
                }
        }
        __syncthreads();
    }

    // ---- epilogue: P -> smem (reuse stage buffers) ----
    float* Psm = smf;   // [128][132]
#pragma unroll
    for (int mt = 0; mt < 4; mt++)
#pragma unroll
        for (int nt = 0; nt < 4; nt++) {
            int row = wm * 64 + mt * 16 + g;
            int col = wn * 32 + nt * 8 + t4 * 2;
            Psm[row * 132 + col]           = acc[mt][nt][0];
            Psm[row * 132 + col + 1]       = acc[mt][nt][1];
            Psm[(row + 8) * 132 + col]     = acc[mt][nt][2];
            Psm[(row + 8) * 132 + col + 1] = acc[mt][nt][3];
        }
    __syncthreads();

    // ---- traversal with borderline flagging ----
    int cb = tid & 31, rg = tid >> 5;
    int c = jT * 32 + cb;
    const float* Tc = &Tg[c * 15];
#pragma unroll
    for (int h8 = 0; h8 < 2; h8++) {
        unsigned long long pk = 0;
#pragma unroll
        for (int rr = 0; rr < 8; rr++) {
            int row = rg * 16 + h8 * 8 + rr;
            float4 fv = *(const float4*)&Psm[row * 132 + cb * 4];
            float f[4] = {fv.x, fv.y, fv.z, fv.w};
            unsigned node = 0, kidx = 0;
            float minabs = 1e30f;
#pragma unroll
            for (int l = 0; l < 4; l++) {
                float d = f[l] - __ldg(&Tc[node]);
                float ad = fabsf(d);
                minabs = (ad < minabs) ? ad : minabs;
                unsigned bit = (d > 0.f) ? 1u : 0u;
                kidx = (kidx << 1) | bit;
                node = 2 * node + 1 + bit;
            }
            pk |= (unsigned long long)kidx << (8 * rr);
            if (minabs < TAU) {
                int slot = atomicAdd(&d_flagCount, 1);
                if (slot < FLAG_CAP)
                    d_flags[slot] = ((unsigned)(nBase + row) << 6) | (unsigned)c;
            }
        }
        *(unsigned long long*)&d_idxT[(size_t)c * Nn + nBase + rg * 16 + h8 * 8] = pk;
    }
}

// ---------------- K1b: exact fp32 fixup, fully unrolled (MLP=16), wide grid ----------------
__global__ __launch_bounds__(256) void k_fixup(
    const float* __restrict__ I, const float* __restrict__ A,
    const float* __restrict__ Tg)
{
    int lane = threadIdx.x & 31;
    int wg = blockIdx.x * 8 + (threadIdx.x >> 5);
    int cnt = d_flagCount;
    if (cnt > FLAG_CAP) cnt = FLAG_CAP;
    for (int e = wg; e < cnt; e += 512 * 8) {
        unsigned v = d_flags[e];
        int n = v >> 6, c = v & 63;
        const float* Irow = &I[(size_t)n * Dd];
        float iv[16];
        float4 av[16];
#pragma unroll
        for (int s = 0; s < 16; s++) {
            int k = s * 32 + lane;
            iv[s] = Irow[k];
            av[s] = *(const float4*)&A[(size_t)k * Jj + c * 4];
        }
        float a0 = 0.f, a1 = 0.f, a2 = 0.f, a3 = 0.f;
#pragma unroll
        for (int s = 0; s < 16; s++) {
            a0 = fmaf(iv[s], av[s].x, a0);
            a1 = fmaf(iv[s], av[s].y, a1);
            a2 = fmaf(iv[s], av[s].z, a2);
            a3 = fmaf(iv[s], av[s].w, a3);
        }
#pragma unroll
        for (int off = 16; off > 0; off >>= 1) {
            a0 += __shfl_xor_sync(0xffffffffu, a0, off);
            a1 += __shfl_xor_sync(0xffffffffu, a1, off);
            a2 += __shfl_xor_sync(0xffffffffu, a2, off);
            a3 += __shfl_xor_sync(0xffffffffu, a3, off);
        }
        if (lane == 0) {
            float f[4] = {a0, a1, a2, a3};
            const float* Tc = &Tg[c * 15];
            unsigned node = 0, kidx = 0;
#pragma unroll
            for (int l = 0; l < 4; l++) {
                unsigned bit = (f[l] > __ldg(&Tc[node])) ? 1u : 0u;
                kidx = (kidx << 1) | bit;
                node = 2 * node + 1 + bit;
            }
            d_idxT[(size_t)c * Nn + n] = (unsigned char)kidx;
        }
    }
}

// ---------------- K2: fp16 HMMA one-hot GEMM (R11 best-measured config) ----------------
#define S2_BPK  0
#define S2_IDX  131072                 // Bpk = 128 KB
#define S2_SMEM (S2_IDX + 2 * 16384)   // 163840 -> 1 CTA/SM

#define NSPLIT 16
#define NPER   (Nn / NSPLIT)           // 2048
#define NROWS  256

__global__ __launch_bounds__(512) void k_lutmma(float* __restrict__ out)
{
    extern __shared__ char sm[];
    unsigned* Bpk = (unsigned*)(sm + S2_BPK);    // [ms8][c64][lane32][2] fp16x2
    uint32_t sb = smaddr(sm);

    int tid  = threadIdx.x;
    int wid  = tid >> 5;
    int lane = tid & 31;
    int g    = lane >> 2;
    int t4   = lane & 3;

    int mBase  = blockIdx.x * 64;
    int nRange = blockIdx.y * NPER;

    {   // copy packed fp16 B slice: 128 KB contiguous (8 mt groups)
        const uint4* src = (const uint4*)&d_Lp16[(size_t)(mBase >> 3) * Cc * 64];
        uint4* dst = (uint4*)Bpk;
        for (int i = tid; i < 8192; i += 512) dst[i] = src[i];
    }

#define COPY_IDX(it, buf)                                                          \
    do {                                                                           \
        int nb_ = nRange + (it) * NROWS;                                           \
        int c_ = tid >> 3, off_ = (tid & 7) * 32;                                  \
        uint32_t d0 = sb + S2_IDX + (buf) * 16384 + c_ * NROWS + off_;             \
        const char* s0 = (const char*)&d_idxT[(size_t)c_ * Nn + nb_ + off_];       \
        cpa16(d0, s0);                                                             \
        cpa16(d0 + 16, s0 + 16);                                                   \
        cp_commit();                                                               \
    } while (0)

    COPY_IDX(0, 0);
    __syncthreads();   // Bpk ready

    int n0loc = wid * 16 + g;
    for (int it = 0; it < NPER / NROWS; it++) {
        if (it < NPER / NROWS - 1) {
            COPY_IDX(it + 1, (it + 1) & 1);
            cp_wait<1>();
        } else {
            cp_wait<0>();
        }
        __syncthreads();
        const unsigned char* idxs = (const unsigned char*)(sm + S2_IDX + (it & 1) * 16384);
        int nb = nRange + it * NROWS;

        float acc[8][4];
#pragma unroll
        for (int ms = 0; ms < 8; ms++)
#pragma unroll
            for (int q = 0; q < 4; q++) acc[ms][q] = 0.f;

#pragma unroll 2
        for (int c = 0; c < Cc; c++) {
            unsigned i0 = idxs[c * NROWS + n0loc];
            unsigned i1 = idxs[c * NROWS + n0loc + 8];
            unsigned s0 = 0x3C00u << ((i0 & 1) << 4);   // fp16 1.0
            unsigned s1 = 0x3C00u << ((i1 & 1) << 4);
            unsigned h0 = i0 >> 1, h1 = i1 >> 1;
            unsigned a0 = (h0 == (unsigned)t4)     ? s0 : 0u;
            unsigned a1 = (h1 == (unsigned)t4)     ? s1 : 0u;
            unsigned a2 = (h0 == (unsigned)t4 + 4) ? s0 : 0u;
            unsigned a3 = (h1 == (unsigned)t4 + 4) ? s1 : 0u;

#pragma unroll
            for (int ms = 0; ms < 8; ms++) {
                uint2 b2 = *(const uint2*)&Bpk[(((ms * Cc + c) * 32) + lane) * 2];
                asm volatile(
                    "mma.sync.aligned.m16n8k16.row.col.f32.f16.f16.f32 "
                    "{%0,%1,%2,%3}, {%4,%5,%6,%7}, {%8,%9}, {%0,%1,%2,%3};"
                    : "+f"(acc[ms][0]), "+f"(acc[ms][1]), "+f"(acc[ms][2]), "+f"(acc[ms][3])
                    : "r"(a0), "r"(a1), "r"(a2), "r"(a3), "r"(b2.x), "r"(b2.y));
            }
        }

        int nA = nb + n0loc;
#pragma unroll
        for (int ms = 0; ms < 8; ms++) {
            float2 v0 = make_float2(acc[ms][0], acc[ms][1]);
            float2 v1 = make_float2(acc[ms][2], acc[ms][3]);
            *(float2*)&out[(size_t)nA * Mm + mBase + ms * 8 + t4 * 2] = v0;
            *(float2*)&out[(size_t)(nA + 8) * Mm + mBase + ms * 8 + t4 * 2] = v1;
        }
        __syncthreads();
    }
}

// ---------------- launch ----------------
extern "C" void kernel_launch(void* const* d_in, const int* in_sizes, int n_in,
                              void* d_out, int out_size) {
    const float *I = nullptr, *T = nullptr, *L = nullptr, *A = nullptr;
    for (int i = 0; i < n_in; i++) {
        switch (in_sizes[i]) {
            case Nn * Dd:      I = (const float*)d_in[i]; break;
            case 960:          T = (const float*)d_in[i]; break;
            case Mm * Cc * Kk: L = (const float*)d_in[i]; break;
            case Dd * Jj:      A = (const float*)d_in[i]; break;
            default: break;  // S, B unused — tree structure hardcoded
        }
    }
    float* out = (float*)d_out;

    cudaFuncSetAttribute(k_gemm_tf32, cudaFuncAttributeMaxDynamicSharedMemorySize, G1_SMEM);
    cudaFuncSetAttribute(k_lutmma,    cudaFuncAttributeMaxDynamicSharedMemorySize, S2_SMEM);

    k_pack<<<(Mm * Cc * Kk / 2) / 256, 256>>>(L);
    k_packA<<<(Dd * Jj / 2) / 256, 256>>>(A);

    dim3 g1(2, Nn / 128);           // (2 jT, 256 nT)
    k_gemm_tf32<<<g1, 256, G1_SMEM>>>(I, T);

    k_fixup<<<512, 256>>>(I, A, T);

    dim3 g2(Mm / 64, NSPLIT);       // (8, 16)
    k_lutmma<<<g2, 512, S2_SMEM>>>(out);
}